// round 8
// baseline (speedup 1.0000x reference)
#include <cuda_runtime.h>
#include <cuda_fp16.h>
#include <math.h>
#include <stdint.h>

#define NN 8192
#define T 64
#define NT (NN / T)                 // 128
#define NPAIRS (NT * (NT + 1) / 2)  // 8256 upper-tri tile pairs

// 16B-granular XOR swizzle for fp32 tiles: phys_chunk = chunk ^ ((row>>2)&7).
#define SWZ(r) (((r) >> 2) & 7)

__device__ float g_part[NT][NN];          // per-slot partial rowsums (4 MB)
__device__ float g_d[NN];
__device__ __half g_m[(size_t)NPAIRS * T * T];   // fp16 m tiles, 64.5 MB

// ---------------------------------------------------------------------------
__device__ __forceinline__ void tri_decode(int t, int& bi, int& bj) {
    float a = 2.0f * NT + 1.0f;
    int b = (int)(0.5f * (a - sqrtf(a * a - 8.0f * (float)t)));
    if (b < 0) b = 0;
    if (b > NT - 1) b = NT - 1;
    while (b > 0 && (b * NT - b * (b - 1) / 2) > t) b--;
    while (((b + 1) * NT - (b + 1) * b / 2) <= t) b++;
    bi = b;
    bj = b + (t - (b * NT - b * (b - 1) / 2));
}

__device__ __forceinline__ void cp_async16(uint32_t dst, const float* src) {
    asm volatile("cp.async.cg.shared.global [%0], [%1], 16;" :: "r"(dst), "l"(src));
}
__device__ __forceinline__ void cp_commit() {
    asm volatile("cp.async.commit_group;" ::: "memory");
}
__device__ __forceinline__ void cp_wait0() {
    asm volatile("cp.async.wait_group 0;" ::: "memory");
}

// Issue one 64x64 fp32 tile load: thread (g = tid>>4, c4 = tid&15) loads 4 rows.
__device__ __forceinline__ void load_tile(uint32_t sbase, const float* __restrict__ src,
                                          int g, int c4) {
    #pragma unroll
    for (int k = 0; k < 4; k++) {
        int row = g + 16 * k;
        uint32_t dst = sbase + (uint32_t)((row * 64 + 4 * (c4 ^ SWZ(row))) * 4);
        cp_async16(dst, src + (size_t)row * NN + 4 * c4);
    }
}

// ---------------------------------------------------------------------------
// Pass 1: compute m = max(adj, adjT) per upper-tri tile pair; accumulate
// row+col partial sums (fp32, exact); persist m as fp16 to g_m.
// ---------------------------------------------------------------------------
__global__ __launch_bounds__(256) void pass1_kernel(const float* __restrict__ adj) {
    __shared__ float s1[T * T];
    __shared__ float s2[T * T];
    __shared__ float rbuf[16][68];   // rbuf[c4][row]
    __shared__ float cbuf[16][68];   // cbuf[g][col]

    int t = blockIdx.x;
    int bi, bj;
    tri_decode(t, bi, bj);
    int tid = threadIdx.x;
    int c4 = tid & 15, g = tid >> 4;
    bool diag = (bi == bj);

    uint32_t s1a = (uint32_t)__cvta_generic_to_shared(s1);
    uint32_t s2a = (uint32_t)__cvta_generic_to_shared(s2);

    load_tile(s1a, adj + (size_t)(bi * T) * NN + (size_t)(bj * T), g, c4);
    if (!diag)
        load_tile(s2a, adj + (size_t)(bj * T) * NN + (size_t)(bi * T), g, c4);
    cp_commit();
    cp_wait0();
    __syncthreads();

    int ca = c4 ^ (g & 7);      // s1 row-patch physical chunk
    int gb = g ^ (c4 & 7);      // transposed-patch physical chunk

    float a[4][4], b[4][4];
    #pragma unroll
    for (int i = 0; i < 4; i++)
        *(float4*)a[i] = *(const float4*)(s1 + (4 * g + i) * 64 + 4 * ca);
    const float* sB = diag ? s1 : s2;
    #pragma unroll
    for (int e = 0; e < 4; e++)
        *(float4*)b[e] = *(const float4*)(sB + (4 * c4 + e) * 64 + 4 * gb);

    float w[4][4];
    float rs[4] = {0, 0, 0, 0}, cs[4] = {0, 0, 0, 0};
    #pragma unroll
    for (int i = 0; i < 4; i++)
        #pragma unroll
        for (int e = 0; e < 4; e++) {
            float v = fmaxf(a[i][e], b[e][i]);
            w[i][e] = v;
            rs[i] += v;
            cs[e] += v;
        }

    // Persist m tile as fp16 (row-major within tile): 4x 8B stores, coalesced.
    // Plain stores: we WANT these L2-resident for pass2 (LIFO consumption).
    __half* mt = g_m + (size_t)t * (T * T);
    #pragma unroll
    for (int i = 0; i < 4; i++) {
        __half2 h0 = __floats2half2_rn(w[i][0], w[i][1]);
        __half2 h1 = __floats2half2_rn(w[i][2], w[i][3]);
        uint2 pk;
        pk.x = *(uint32_t*)&h0;
        pk.y = *(uint32_t*)&h1;
        *(uint2*)(mt + (4 * g + i) * T + 4 * c4) = pk;
    }

    *(float4*)&rbuf[c4][4 * g] = make_float4(rs[0], rs[1], rs[2], rs[3]);
    *(float4*)&cbuf[g][4 * c4] = make_float4(cs[0], cs[1], cs[2], cs[3]);
    __syncthreads();

    if (tid < T) {
        float s = 0.0f;
        #pragma unroll
        for (int k = 0; k < 16; k++) s += rbuf[k][tid];
        g_part[bj][bi * T + tid] = s;            // rows of block bi
    } else if (!diag && tid < 2 * T) {
        int u = tid - T;
        float s = 0.0f;
        #pragma unroll
        for (int k = 0; k < 16; k++) s += cbuf[k][u];
        g_part[bi][bj * T + u] = s;              // rows of block bj
    }
}

// ---------------------------------------------------------------------------
// d[i] = (1 + sum_k part[k][i])^-1/2   (rowsum >= 1, never inf)
// ---------------------------------------------------------------------------
__global__ __launch_bounds__(256) void reduce_d_kernel() {
    int i4 = blockIdx.x * blockDim.x + threadIdx.x;   // float4 index
    float4 s = make_float4(1.0f, 1.0f, 1.0f, 1.0f);   // self-loops
    #pragma unroll 4
    for (int k = 0; k < NT; k++) {
        float4 p = *(const float4*)&g_part[k][4 * i4];
        s.x += p.x; s.y += p.y; s.z += p.z; s.w += p.w;
    }
    float4 d = make_float4(rsqrtf(s.x), rsqrtf(s.y), rsqrtf(s.z), rsqrtf(s.w));
    *(float4*)&g_d[4 * i4] = d;
}

// ---------------------------------------------------------------------------
// Pass 2: out = d[i]*d[j]*(m + I), reading fp16 m. Tiles consumed in REVERSE
// order (LIFO vs pass1's writes) so the L2-resident tail of g_m is hit.
// d read directly (L1-resident broadcast); out written with streaming stores.
// ---------------------------------------------------------------------------
__global__ __launch_bounds__(256) void pass2_kernel(float* __restrict__ out) {
    __shared__ float st[T * T];      // transposed-output staging (swizzled)

    int t = NPAIRS - 1 - blockIdx.x;   // reverse order: maximize L2 hits on g_m
    int bi, bj;
    tri_decode(t, bi, bj);
    int tid = threadIdx.x;
    int c4 = tid & 15, g = tid >> 4;
    bool diag = (bi == bj);

    // Issue m loads first (the only potential DRAM reads in this block).
    const __half* mt = g_m + (size_t)t * (T * T);
    uint2 pk[4];
    #pragma unroll
    for (int i = 0; i < 4; i++)
        pk[i] = *(const uint2*)(mt + (4 * g + i) * T + 4 * c4);

    // d factors: broadcast loads, L1/L2-resident (32 KB vector).
    float dA[4], dB[4];
    #pragma unroll
    for (int i = 0; i < 4; i++) dA[i] = __ldg(&g_d[bi * T + 4 * g + i]);
    #pragma unroll
    for (int e = 0; e < 4; e++) dB[e] = __ldg(&g_d[bj * T + 4 * c4 + e]);

    float w[4][4];
    #pragma unroll
    for (int i = 0; i < 4; i++) {
        __half2 h0 = *(__half2*)&pk[i].x;
        __half2 h1 = *(__half2*)&pk[i].y;
        float2 f0 = __half22float2(h0);
        float2 f1 = __half22float2(h1);
        w[i][0] = f0.x; w[i][1] = f0.y; w[i][2] = f1.x; w[i][3] = f1.y;
    }

    #pragma unroll
    for (int i = 0; i < 4; i++)
        #pragma unroll
        for (int e = 0; e < 4; e++) {
            float v = w[i][e];
            if (diag && g == c4 && i == e) v += 1.0f;
            w[i][e] = dA[i] * dB[e] * v;
        }

    // Upper output tile (rows of block bi): coalesced streaming STG.128
    float* po1 = out + (size_t)(bi * T) * NN + (size_t)(bj * T);
    #pragma unroll
    for (int i = 0; i < 4; i++)
        __stcs((float4*)(po1 + (size_t)(4 * g + i) * NN + 4 * c4), *(float4*)w[i]);

    if (!diag) {
        // Lower tile = w transposed: stage through swizzled smem, write coalesced.
        int ca = c4 ^ (g & 7);
        int gb = g ^ (c4 & 7);
        #pragma unroll
        for (int e = 0; e < 4; e++)
            *(float4*)(st + (4 * c4 + e) * 64 + 4 * gb) =
                make_float4(w[0][e], w[1][e], w[2][e], w[3][e]);
        __syncthreads();

        float* po2 = out + (size_t)(bj * T) * NN + (size_t)(bi * T);
        #pragma unroll
        for (int i = 0; i < 4; i++) {
            float4 o = *(const float4*)(st + (4 * g + i) * 64 + 4 * ca);
            __stcs((float4*)(po2 + (size_t)(4 * g + i) * NN + 4 * c4), o);
        }
    }
}

extern "C" void kernel_launch(void* const* d_in, const int* in_sizes, int n_in,
                              void* d_out, int out_size) {
    const float* adj = (const float*)d_in[0];
    float* out = (float*)d_out;
    (void)in_sizes; (void)n_in; (void)out_size;

    pass1_kernel<<<NPAIRS, 256>>>(adj);
    reduce_d_kernel<<<NN / 4 / 256, 256>>>();
    pass2_kernel<<<NPAIRS, 256>>>(out);
}

// round 9
// speedup vs baseline: 1.1198x; 1.1198x over previous
#include <cuda_runtime.h>
#include <cuda_fp16.h>
#include <math.h>
#include <stdint.h>

#define NN 8192
#define T 64
#define NT (NN / T)                 // 128
#define NPAIRS (NT * (NT + 1) / 2)  // 8256 upper-tri tile pairs

// 16B-granular XOR swizzle for fp32 tiles: phys_chunk = chunk ^ ((row>>2)&7).
#define SWZ(r) (((r) >> 2) & 7)

__device__ float g_part[NT][NN];          // per-slot partial rowsums (4 MB)
__device__ float g_d[NN];
__device__ __half g_m[(size_t)NPAIRS * T * T];   // fp16 m tiles, 64.5 MB

// ---------------------------------------------------------------------------
__device__ __forceinline__ void tri_decode(int t, int& bi, int& bj) {
    float a = 2.0f * NT + 1.0f;
    int b = (int)(0.5f * (a - sqrtf(a * a - 8.0f * (float)t)));
    if (b < 0) b = 0;
    if (b > NT - 1) b = NT - 1;
    while (b > 0 && (b * NT - b * (b - 1) / 2) > t) b--;
    while (((b + 1) * NT - (b + 1) * b / 2) <= t) b++;
    bi = b;
    bj = b + (t - (b * NT - b * (b - 1) / 2));
}

// cp.async with L2 evict-first policy: adj is read-once, keep it OUT of L2
// so the g_m write stream stays resident for pass2.
__device__ __forceinline__ uint64_t mk_evict_first() {
    uint64_t pol;
    asm("createpolicy.fractional.L2::evict_first.b64 %0, 1.0;" : "=l"(pol));
    return pol;
}
__device__ __forceinline__ void cp_async16_ef(uint32_t dst, const float* src, uint64_t pol) {
    asm volatile("cp.async.cg.shared.global.L2::cache_hint [%0], [%1], 16, %2;"
                 :: "r"(dst), "l"(src), "l"(pol));
}
__device__ __forceinline__ void cp_commit() {
    asm volatile("cp.async.commit_group;" ::: "memory");
}
__device__ __forceinline__ void cp_wait0() {
    asm volatile("cp.async.wait_group 0;" ::: "memory");
}

// Issue one 64x64 fp32 tile load: thread (g = tid>>4, c4 = tid&15) loads 4 rows.
__device__ __forceinline__ void load_tile(uint32_t sbase, const float* __restrict__ src,
                                          int g, int c4, uint64_t pol) {
    #pragma unroll
    for (int k = 0; k < 4; k++) {
        int row = g + 16 * k;
        uint32_t dst = sbase + (uint32_t)((row * 64 + 4 * (c4 ^ SWZ(row))) * 4);
        cp_async16_ef(dst, src + (size_t)row * NN + 4 * c4, pol);
    }
}

// ---------------------------------------------------------------------------
// Pass 1: compute m = max(adj, adjT) per upper-tri tile pair; accumulate
// row+col partial sums (fp32, exact); persist m as fp16 to g_m.
// adj loads are L2-evict-first; m writes are normal (stay L2-resident).
// ---------------------------------------------------------------------------
__global__ __launch_bounds__(256) void pass1_kernel(const float* __restrict__ adj) {
    __shared__ float s1[T * T];
    __shared__ float s2[T * T];
    __shared__ float rbuf[16][68];   // rbuf[c4][row]
    __shared__ float cbuf[16][68];   // cbuf[g][col]

    int t = blockIdx.x;
    int bi, bj;
    tri_decode(t, bi, bj);
    int tid = threadIdx.x;
    int c4 = tid & 15, g = tid >> 4;
    bool diag = (bi == bj);
    uint64_t pol = mk_evict_first();

    uint32_t s1a = (uint32_t)__cvta_generic_to_shared(s1);
    uint32_t s2a = (uint32_t)__cvta_generic_to_shared(s2);

    load_tile(s1a, adj + (size_t)(bi * T) * NN + (size_t)(bj * T), g, c4, pol);
    if (!diag)
        load_tile(s2a, adj + (size_t)(bj * T) * NN + (size_t)(bi * T), g, c4, pol);
    cp_commit();
    cp_wait0();
    __syncthreads();

    int ca = c4 ^ (g & 7);      // s1 row-patch physical chunk
    int gb = g ^ (c4 & 7);      // transposed-patch physical chunk

    float a[4][4], b[4][4];
    #pragma unroll
    for (int i = 0; i < 4; i++)
        *(float4*)a[i] = *(const float4*)(s1 + (4 * g + i) * 64 + 4 * ca);
    const float* sB = diag ? s1 : s2;
    #pragma unroll
    for (int e = 0; e < 4; e++)
        *(float4*)b[e] = *(const float4*)(sB + (4 * c4 + e) * 64 + 4 * gb);

    float w[4][4];
    float rs[4] = {0, 0, 0, 0}, cs[4] = {0, 0, 0, 0};
    #pragma unroll
    for (int i = 0; i < 4; i++)
        #pragma unroll
        for (int e = 0; e < 4; e++) {
            float v = fmaxf(a[i][e], b[e][i]);
            w[i][e] = v;
            rs[i] += v;
            cs[e] += v;
        }

    // Persist m tile as fp16 (row-major within tile): 4x 8B stores, coalesced.
    // Normal stores — these SHOULD be L2-resident for pass2 (LIFO consumption).
    __half* mt = g_m + (size_t)t * (T * T);
    #pragma unroll
    for (int i = 0; i < 4; i++) {
        __half2 h0 = __floats2half2_rn(w[i][0], w[i][1]);
        __half2 h1 = __floats2half2_rn(w[i][2], w[i][3]);
        uint2 pk;
        pk.x = *(uint32_t*)&h0;
        pk.y = *(uint32_t*)&h1;
        *(uint2*)(mt + (4 * g + i) * T + 4 * c4) = pk;
    }

    *(float4*)&rbuf[c4][4 * g] = make_float4(rs[0], rs[1], rs[2], rs[3]);
    *(float4*)&cbuf[g][4 * c4] = make_float4(cs[0], cs[1], cs[2], cs[3]);
    __syncthreads();

    if (tid < T) {
        float s = 0.0f;
        #pragma unroll
        for (int k = 0; k < 16; k++) s += rbuf[k][tid];
        g_part[bj][bi * T + tid] = s;            // rows of block bi
    } else if (!diag && tid < 2 * T) {
        int u = tid - T;
        float s = 0.0f;
        #pragma unroll
        for (int k = 0; k < 16; k++) s += cbuf[k][u];
        g_part[bi][bj * T + u] = s;              // rows of block bj
    }
}

// ---------------------------------------------------------------------------
// d[i] = (1 + sum_k part[k][i])^-1/2   (rowsum >= 1, never inf)
// g_part reads use __ldcs: read-once, don't evict m from L2.
// ---------------------------------------------------------------------------
__global__ __launch_bounds__(256) void reduce_d_kernel() {
    int i4 = blockIdx.x * blockDim.x + threadIdx.x;   // float4 index
    float4 s = make_float4(1.0f, 1.0f, 1.0f, 1.0f);   // self-loops
    #pragma unroll 4
    for (int k = 0; k < NT; k++) {
        float4 p = __ldcs((const float4*)&g_part[k][4 * i4]);
        s.x += p.x; s.y += p.y; s.z += p.z; s.w += p.w;
    }
    float4 d = make_float4(rsqrtf(s.x), rsqrtf(s.y), rsqrtf(s.z), rsqrtf(s.w));
    *(float4*)&g_d[4 * i4] = d;
}

// ---------------------------------------------------------------------------
// Pass 2: out = d[i]*d[j]*(m + I), reading fp16 m (mostly L2 hits now).
// Tiles consumed in REVERSE order (LIFO vs pass1's writes). out written with
// streaming (evict-first) stores so they don't displace m.
// ---------------------------------------------------------------------------
__global__ __launch_bounds__(256) void pass2_kernel(float* __restrict__ out) {
    __shared__ float st[T * T];      // transposed-output staging (swizzled)

    int t = NPAIRS - 1 - blockIdx.x;   // reverse order: maximize L2 hits on g_m
    int bi, bj;
    tri_decode(t, bi, bj);
    int tid = threadIdx.x;
    int c4 = tid & 15, g = tid >> 4;
    bool diag = (bi == bj);

    // Issue m loads first.
    const __half* mt = g_m + (size_t)t * (T * T);
    uint2 pk[4];
    #pragma unroll
    for (int i = 0; i < 4; i++)
        pk[i] = *(const uint2*)(mt + (4 * g + i) * T + 4 * c4);

    // d factors: broadcast loads, L1/L2-resident (32 KB vector).
    float dA[4], dB[4];
    #pragma unroll
    for (int i = 0; i < 4; i++) dA[i] = __ldg(&g_d[bi * T + 4 * g + i]);
    #pragma unroll
    for (int e = 0; e < 4; e++) dB[e] = __ldg(&g_d[bj * T + 4 * c4 + e]);

    float w[4][4];
    #pragma unroll
    for (int i = 0; i < 4; i++) {
        __half2 h0 = *(__half2*)&pk[i].x;
        __half2 h1 = *(__half2*)&pk[i].y;
        float2 f0 = __half22float2(h0);
        float2 f1 = __half22float2(h1);
        w[i][0] = f0.x; w[i][1] = f0.y; w[i][2] = f1.x; w[i][3] = f1.y;
    }

    #pragma unroll
    for (int i = 0; i < 4; i++)
        #pragma unroll
        for (int e = 0; e < 4; e++) {
            float v = w[i][e];
            if (diag && g == c4 && i == e) v += 1.0f;
            w[i][e] = dA[i] * dB[e] * v;
        }

    // Upper output tile (rows of block bi): coalesced streaming STG.128
    float* po1 = out + (size_t)(bi * T) * NN + (size_t)(bj * T);
    #pragma unroll
    for (int i = 0; i < 4; i++)
        __stcs((float4*)(po1 + (size_t)(4 * g + i) * NN + 4 * c4), *(float4*)w[i]);

    if (!diag) {
        // Lower tile = w transposed: stage through swizzled smem, write coalesced.
        int ca = c4 ^ (g & 7);
        int gb = g ^ (c4 & 7);
        #pragma unroll
        for (int e = 0; e < 4; e++)
            *(float4*)(st + (4 * c4 + e) * 64 + 4 * gb) =
                make_float4(w[0][e], w[1][e], w[2][e], w[3][e]);
        __syncthreads();

        float* po2 = out + (size_t)(bj * T) * NN + (size_t)(bi * T);
        #pragma unroll
        for (int i = 0; i < 4; i++) {
            float4 o = *(const float4*)(st + (4 * g + i) * 64 + 4 * ca);
            __stcs((float4*)(po2 + (size_t)(4 * g + i) * NN + 4 * c4), o);
        }
    }
}

extern "C" void kernel_launch(void* const* d_in, const int* in_sizes, int n_in,
                              void* d_out, int out_size) {
    const float* adj = (const float*)d_in[0];
    float* out = (float*)d_out;
    (void)in_sizes; (void)n_in; (void)out_size;

    pass1_kernel<<<NPAIRS, 256>>>(adj);
    reduce_d_kernel<<<NN / 4 / 256, 256>>>();
    pass2_kernel<<<NPAIRS, 256>>>(out);
}